// round 4
// baseline (speedup 1.0000x reference)
#include <cuda_runtime.h>
#include <math.h>

#define N_NODES 100000
#define N_EDGES 3200000
#define IN_F 256
#define OUT_F 64
#define ALPHA 0.2f

// Scratch (static device globals: allocation-free)
__device__ float g_h[(size_t)N_NODES * OUT_F];     // 25.6 MB
__device__ float g_acc[(size_t)N_NODES * OUT_F];   // 25.6 MB accumulator
__device__ float g_ssrc[N_NODES];
__device__ float g_sdst[N_NODES];
__device__ float g_rowsum[N_NODES];

// ---------------------------------------------------------------------------
// Zero: accumulator + rowsum
// ---------------------------------------------------------------------------
__global__ void zero_kernel() {
    int i  = blockIdx.x * blockDim.x + threadIdx.x;
    int nt = gridDim.x * blockDim.x;
    const float4 z = make_float4(0.f, 0.f, 0.f, 0.f);
    for (int j = i; j < N_NODES * OUT_F / 4; j += nt) ((float4*)g_acc)[j] = z;
    for (int j = i; j < N_NODES / 4; j += nt)         ((float4*)g_rowsum)[j] = z;
}

// ---------------------------------------------------------------------------
// GEMM: h = input @ W  (64x64 tile per block, 4x4 register tile per thread)
// ---------------------------------------------------------------------------
__global__ __launch_bounds__(256) void gemm_kernel(const float* __restrict__ inp,
                                                   const float* __restrict__ W) {
    __shared__ float As[32][64];   // [k][row]  (transposed input tile)
    __shared__ float Bs[32][64];   // [k][col]
    const int tid = threadIdx.x;
    const int tx  = tid & 15;      // col group (4 cols)
    const int ty  = tid >> 4;      // row group (4 rows)
    const int rowbase = blockIdx.x * 64;

    float acc[4][4];
#pragma unroll
    for (int r = 0; r < 4; r++)
#pragma unroll
        for (int c = 0; c < 4; c++) acc[r][c] = 0.f;

    for (int kb = 0; kb < IN_F; kb += 32) {
        // Load A tile 64 rows x 32 k (transpose into smem)
#pragma unroll
        for (int i = 0; i < 2; i++) {
            int idx = tid * 2 + i;        // 0..511
            int r   = idx >> 3;           // 0..63
            int kq  = idx & 7;            // k-quad
            int grow = rowbase + r;
            float4 v = make_float4(0.f, 0.f, 0.f, 0.f);
            if (grow < N_NODES)
                v = *(const float4*)(inp + (size_t)grow * IN_F + kb + kq * 4);
            As[kq * 4 + 0][r] = v.x;
            As[kq * 4 + 1][r] = v.y;
            As[kq * 4 + 2][r] = v.z;
            As[kq * 4 + 3][r] = v.w;
        }
        // Load B tile 32 k x 64 cols
#pragma unroll
        for (int i = 0; i < 2; i++) {
            int idx = tid * 2 + i;
            int kk  = idx >> 4;           // 0..31
            int cq  = idx & 15;           // col-quad
            *(float4*)&Bs[kk][cq * 4] =
                *(const float4*)(W + (size_t)(kb + kk) * OUT_F + cq * 4);
        }
        __syncthreads();
#pragma unroll
        for (int kk = 0; kk < 32; kk++) {
            float4 a = *(float4*)&As[kk][ty * 4];
            float4 b = *(float4*)&Bs[kk][tx * 4];
            acc[0][0] += a.x * b.x; acc[0][1] += a.x * b.y; acc[0][2] += a.x * b.z; acc[0][3] += a.x * b.w;
            acc[1][0] += a.y * b.x; acc[1][1] += a.y * b.y; acc[1][2] += a.y * b.z; acc[1][3] += a.y * b.w;
            acc[2][0] += a.z * b.x; acc[2][1] += a.z * b.y; acc[2][2] += a.z * b.z; acc[2][3] += a.z * b.w;
            acc[3][0] += a.w * b.x; acc[3][1] += a.w * b.y; acc[3][2] += a.w * b.z; acc[3][3] += a.w * b.w;
        }
        __syncthreads();
    }
#pragma unroll
    for (int r = 0; r < 4; r++) {
        int grow = rowbase + ty * 4 + r;
        if (grow < N_NODES)
            *(float4*)&g_h[(size_t)grow * OUT_F + tx * 4] =
                make_float4(acc[r][0], acc[r][1], acc[r][2], acc[r][3]);
    }
}

// ---------------------------------------------------------------------------
// Scores: s_src[i] = h[i]·a[0:64], s_dst[i] = h[i]·a[64:128]   (1 warp / row)
// ---------------------------------------------------------------------------
__global__ __launch_bounds__(256) void score_kernel(const float* __restrict__ a) {
    int warp = (blockIdx.x * blockDim.x + threadIdx.x) >> 5;
    int lane = threadIdx.x & 31;
    if (warp >= N_NODES) return;
    float h0 = g_h[(size_t)warp * OUT_F + lane];
    float h1 = g_h[(size_t)warp * OUT_F + 32 + lane];
    float ss = h0 * a[lane]      + h1 * a[32 + lane];
    float sd = h0 * a[64 + lane] + h1 * a[96 + lane];
#pragma unroll
    for (int o = 16; o; o >>= 1) {
        ss += __shfl_down_sync(0xFFFFFFFFu, ss, o);
        sd += __shfl_down_sync(0xFFFFFFFFu, sd, o);
    }
    if (lane == 0) { g_ssrc[warp] = ss; g_sdst[warp] = sd; }
}

// ---------------------------------------------------------------------------
// Edge scatter: 16 lanes per edge, float4 gather + 4 scalar atomicAdd each
// edge indices are int32 (JAX x64 disabled downcasts int64 -> int32)
// ---------------------------------------------------------------------------
__global__ __launch_bounds__(256) void edge_kernel(const int* __restrict__ esrc,
                                                   const int* __restrict__ edst) {
    long long gtid = (long long)blockIdx.x * blockDim.x + threadIdx.x;
    int e = (int)(gtid >> 4);
    int l = (int)(gtid & 15);
    if (e >= N_EDGES) return;

    int s = esrc[e];
    int d = edst[e];
    if ((unsigned)s >= N_NODES || (unsigned)d >= N_NODES) return;  // dtype insurance

    float sc = g_ssrc[s] + g_sdst[d];
    float lr = sc > 0.f ? sc : ALPHA * sc;
    float ee = __expf(-lr);

    if (l == 0) atomicAdd(&g_rowsum[s], ee);

    float4 v = *(const float4*)(g_h + (size_t)d * OUT_F + l * 4);
    float* op = g_acc + (size_t)s * OUT_F + l * 4;
    atomicAdd(op + 0, v.x * ee);
    atomicAdd(op + 1, v.y * ee);
    atomicAdd(op + 2, v.z * ee);
    atomicAdd(op + 3, v.w * ee);
}

// ---------------------------------------------------------------------------
// Finalize: out = elu(acc / rowsum)  (plain stores into d_out)
// ---------------------------------------------------------------------------
__global__ __launch_bounds__(256) void finalize_kernel(float* __restrict__ out) {
    int i = blockIdx.x * blockDim.x + threadIdx.x;
    const int total = N_NODES * OUT_F / 4;
    if (i >= total) return;
    float4 v = ((const float4*)g_acc)[i];
    float inv = 1.f / g_rowsum[i >> 4];   // 16 float4 per row
    v.x *= inv; v.y *= inv; v.z *= inv; v.w *= inv;
    v.x = v.x > 0.f ? v.x : expm1f(v.x);
    v.y = v.y > 0.f ? v.y : expm1f(v.y);
    v.z = v.z > 0.f ? v.z : expm1f(v.z);
    v.w = v.w > 0.f ? v.w : expm1f(v.w);
    ((float4*)out)[i] = v;
}

// ---------------------------------------------------------------------------
extern "C" void kernel_launch(void* const* d_in, const int* in_sizes, int n_in,
                              void* d_out, int out_size) {
    const float* inp  = (const float*)d_in[0];
    const int*   edge = (const int*)d_in[1];     // int32 (JAX default x64-off)
    const float* W    = (const float*)d_in[2];
    const float* a    = (const float*)d_in[3];
    float*       out  = (float*)d_out;

    const int* esrc = edge;
    const int* edst = edge + N_EDGES;

    zero_kernel<<<1024, 256>>>();
    gemm_kernel<<<(N_NODES + 63) / 64, 256>>>(inp, W);
    score_kernel<<<(N_NODES * 32 + 255) / 256, 256>>>(a);
    {
        long long threads = (long long)N_EDGES * 16;
        int blocks = (int)((threads + 255) / 256);
        edge_kernel<<<blocks, 256>>>(esrc, edst);
    }
    finalize_kernel<<<(N_NODES * OUT_F / 4 + 255) / 256, 256>>>(out);
}

// round 5
// speedup vs baseline: 2.1141x; 2.1141x over previous
#include <cuda_runtime.h>
#include <math.h>

#define N_NODES 100000
#define N_EDGES 3200000
#define IN_F 256
#define OUT_F 64
#define ALPHA 0.2f
#define SCAN_BLK 1024
#define N_SCAN_BLOCKS ((N_NODES + SCAN_BLK - 1) / SCAN_BLK)   // 98

// Scratch (static device globals: allocation-free)
__device__ float  g_h[(size_t)N_NODES * OUT_F];    // 25.6 MB
__device__ float  g_ssrc[N_NODES];
__device__ float  g_sdst[N_NODES];
__device__ int    g_count[N_NODES];
__device__ int    g_start[N_NODES];
__device__ int    g_cursor[N_NODES];
__device__ int    g_bsum[N_SCAN_BLOCKS];
__device__ int    g_boff[N_SCAN_BLOCKS];
__device__ float2 g_edge[N_EDGES];                 // (.x = dst as int bits, .y = ee)

// ---------------------------------------------------------------------------
// Zero histogram counters
// ---------------------------------------------------------------------------
__global__ void zero_kernel() {
    int i = blockIdx.x * blockDim.x + threadIdx.x;
    if (i < N_NODES) g_count[i] = 0;
}

// ---------------------------------------------------------------------------
// GEMM: h = input @ W  (64x64 tile per block, 4x4 register tile per thread)
// ---------------------------------------------------------------------------
__global__ __launch_bounds__(256) void gemm_kernel(const float* __restrict__ inp,
                                                   const float* __restrict__ W) {
    __shared__ float As[32][64];   // [k][row]  (transposed input tile)
    __shared__ float Bs[32][64];   // [k][col]
    const int tid = threadIdx.x;
    const int tx  = tid & 15;      // col group (4 cols)
    const int ty  = tid >> 4;      // row group (4 rows)
    const int rowbase = blockIdx.x * 64;

    float acc[4][4];
#pragma unroll
    for (int r = 0; r < 4; r++)
#pragma unroll
        for (int c = 0; c < 4; c++) acc[r][c] = 0.f;

    for (int kb = 0; kb < IN_F; kb += 32) {
#pragma unroll
        for (int i = 0; i < 2; i++) {
            int idx = tid * 2 + i;        // 0..511
            int r   = idx >> 3;           // 0..63
            int kq  = idx & 7;            // k-quad
            int grow = rowbase + r;
            float4 v = make_float4(0.f, 0.f, 0.f, 0.f);
            if (grow < N_NODES)
                v = *(const float4*)(inp + (size_t)grow * IN_F + kb + kq * 4);
            As[kq * 4 + 0][r] = v.x;
            As[kq * 4 + 1][r] = v.y;
            As[kq * 4 + 2][r] = v.z;
            As[kq * 4 + 3][r] = v.w;
        }
#pragma unroll
        for (int i = 0; i < 2; i++) {
            int idx = tid * 2 + i;
            int kk  = idx >> 4;           // 0..31
            int cq  = idx & 15;           // col-quad
            *(float4*)&Bs[kk][cq * 4] =
                *(const float4*)(W + (size_t)(kb + kk) * OUT_F + cq * 4);
        }
        __syncthreads();
#pragma unroll
        for (int kk = 0; kk < 32; kk++) {
            float4 a = *(float4*)&As[kk][ty * 4];
            float4 b = *(float4*)&Bs[kk][tx * 4];
            acc[0][0] += a.x * b.x; acc[0][1] += a.x * b.y; acc[0][2] += a.x * b.z; acc[0][3] += a.x * b.w;
            acc[1][0] += a.y * b.x; acc[1][1] += a.y * b.y; acc[1][2] += a.y * b.z; acc[1][3] += a.y * b.w;
            acc[2][0] += a.z * b.x; acc[2][1] += a.z * b.y; acc[2][2] += a.z * b.z; acc[2][3] += a.z * b.w;
            acc[3][0] += a.w * b.x; acc[3][1] += a.w * b.y; acc[3][2] += a.w * b.z; acc[3][3] += a.w * b.w;
        }
        __syncthreads();
    }
#pragma unroll
    for (int r = 0; r < 4; r++) {
        int grow = rowbase + ty * 4 + r;
        if (grow < N_NODES)
            *(float4*)&g_h[(size_t)grow * OUT_F + tx * 4] =
                make_float4(acc[r][0], acc[r][1], acc[r][2], acc[r][3]);
    }
}

// ---------------------------------------------------------------------------
// Scores: s_src[i] = h[i]·a[0:64], s_dst[i] = h[i]·a[64:128]   (1 warp / row)
// ---------------------------------------------------------------------------
__global__ __launch_bounds__(256) void score_kernel(const float* __restrict__ a) {
    int warp = (blockIdx.x * blockDim.x + threadIdx.x) >> 5;
    int lane = threadIdx.x & 31;
    if (warp >= N_NODES) return;
    float h0 = g_h[(size_t)warp * OUT_F + lane];
    float h1 = g_h[(size_t)warp * OUT_F + 32 + lane];
    float ss = h0 * a[lane]      + h1 * a[32 + lane];
    float sd = h0 * a[64 + lane] + h1 * a[96 + lane];
#pragma unroll
    for (int o = 16; o; o >>= 1) {
        ss += __shfl_down_sync(0xFFFFFFFFu, ss, o);
        sd += __shfl_down_sync(0xFFFFFFFFu, sd, o);
    }
    if (lane == 0) { g_ssrc[warp] = ss; g_sdst[warp] = sd; }
}

// ---------------------------------------------------------------------------
// Histogram of src
// ---------------------------------------------------------------------------
__global__ __launch_bounds__(256) void hist_kernel(const int* __restrict__ esrc) {
    int e = blockIdx.x * blockDim.x + threadIdx.x;
    if (e >= N_EDGES) return;
    int s = esrc[e];
    if ((unsigned)s < N_NODES) atomicAdd(&g_count[s], 1);
}

// ---------------------------------------------------------------------------
// Exclusive scan (3 kernels)
// ---------------------------------------------------------------------------
__global__ __launch_bounds__(SCAN_BLK) void scan1_kernel() {
    __shared__ int sm[SCAN_BLK];
    int tid = threadIdx.x;
    int gid = blockIdx.x * SCAN_BLK + tid;
    int v = (gid < N_NODES) ? g_count[gid] : 0;
    sm[tid] = v;
    __syncthreads();
#pragma unroll
    for (int off = 1; off < SCAN_BLK; off <<= 1) {
        int t = (tid >= off) ? sm[tid - off] : 0;
        __syncthreads();
        sm[tid] += t;
        __syncthreads();
    }
    if (gid < N_NODES) g_start[gid] = sm[tid] - v;  // exclusive
    if (tid == SCAN_BLK - 1) g_bsum[blockIdx.x] = sm[tid];
}

__global__ void scan2_kernel() {
    if (threadIdx.x == 0) {
        int run = 0;
        for (int b = 0; b < N_SCAN_BLOCKS; b++) {
            int t = g_bsum[b];
            g_boff[b] = run;
            run += t;
        }
    }
}

__global__ __launch_bounds__(256) void scan3_kernel() {
    int i = blockIdx.x * blockDim.x + threadIdx.x;
    if (i >= N_NODES) return;
    int st = g_start[i] + g_boff[i >> 10];
    g_start[i]  = st;
    g_cursor[i] = st;
}

// ---------------------------------------------------------------------------
// Scatter: place (dst, ee) into CSR slot of src
// ---------------------------------------------------------------------------
__global__ __launch_bounds__(256) void scatter_kernel(const int* __restrict__ esrc,
                                                      const int* __restrict__ edst) {
    int e = blockIdx.x * blockDim.x + threadIdx.x;
    if (e >= N_EDGES) return;
    int s = esrc[e];
    int d = edst[e];
    if ((unsigned)s >= N_NODES || (unsigned)d >= N_NODES) return;

    float sc = g_ssrc[s] + g_sdst[d];
    float lr = sc > 0.f ? sc : ALPHA * sc;
    float ee = __expf(-lr);

    int pos = atomicAdd(&g_cursor[s], 1);
    g_edge[pos] = make_float2(__int_as_float(d), ee);
}

// ---------------------------------------------------------------------------
// Aggregate: 1 warp per node, no atomics; fused rowsum + divide + ELU + store
// ---------------------------------------------------------------------------
__global__ __launch_bounds__(256) void aggregate_kernel(float* __restrict__ out) {
    int node = (blockIdx.x * blockDim.x + threadIdx.x) >> 5;
    int lane = threadIdx.x & 31;
    if (node >= N_NODES) return;

    int start = g_start[node];
    int end   = start + g_count[node];

    float acc0 = 0.f, acc1 = 0.f, rs = 0.f;
    int i = start;
    for (; i + 4 <= end; i += 4) {
        float2 e0 = g_edge[i + 0];
        float2 e1 = g_edge[i + 1];
        float2 e2 = g_edge[i + 2];
        float2 e3 = g_edge[i + 3];
        int d0 = __float_as_int(e0.x);
        int d1 = __float_as_int(e1.x);
        int d2 = __float_as_int(e2.x);
        int d3 = __float_as_int(e3.x);
        float h00 = g_h[(size_t)d0 * OUT_F + lane];
        float h01 = g_h[(size_t)d0 * OUT_F + 32 + lane];
        float h10 = g_h[(size_t)d1 * OUT_F + lane];
        float h11 = g_h[(size_t)d1 * OUT_F + 32 + lane];
        float h20 = g_h[(size_t)d2 * OUT_F + lane];
        float h21 = g_h[(size_t)d2 * OUT_F + 32 + lane];
        float h30 = g_h[(size_t)d3 * OUT_F + lane];
        float h31 = g_h[(size_t)d3 * OUT_F + 32 + lane];
        acc0 += e0.y * h00; acc1 += e0.y * h01;
        acc0 += e1.y * h10; acc1 += e1.y * h11;
        acc0 += e2.y * h20; acc1 += e2.y * h21;
        acc0 += e3.y * h30; acc1 += e3.y * h31;
        rs += e0.y + e1.y + e2.y + e3.y;
    }
    for (; i < end; i++) {
        float2 er = g_edge[i];
        int d = __float_as_int(er.x);
        acc0 += er.y * g_h[(size_t)d * OUT_F + lane];
        acc1 += er.y * g_h[(size_t)d * OUT_F + 32 + lane];
        rs += er.y;
    }

    float inv = 1.f / rs;
    float o0 = acc0 * inv;
    float o1 = acc1 * inv;
    o0 = o0 > 0.f ? o0 : expm1f(o0);
    o1 = o1 > 0.f ? o1 : expm1f(o1);
    out[(size_t)node * OUT_F + lane]      = o0;
    out[(size_t)node * OUT_F + 32 + lane] = o1;
}

// ---------------------------------------------------------------------------
extern "C" void kernel_launch(void* const* d_in, const int* in_sizes, int n_in,
                              void* d_out, int out_size) {
    const float* inp  = (const float*)d_in[0];
    const int*   edge = (const int*)d_in[1];     // int32 (JAX default x64-off)
    const float* W    = (const float*)d_in[2];
    const float* a    = (const float*)d_in[3];
    float*       out  = (float*)d_out;

    const int* esrc = edge;
    const int* edst = edge + N_EDGES;

    const int EB = (N_EDGES + 255) / 256;          // 12500
    const int NB = (N_NODES + 255) / 256;          // 391

    zero_kernel<<<NB, 256>>>();
    gemm_kernel<<<(N_NODES + 63) / 64, 256>>>(inp, W);
    score_kernel<<<(N_NODES * 32 + 255) / 256, 256>>>(a);
    hist_kernel<<<EB, 256>>>(esrc);
    scan1_kernel<<<N_SCAN_BLOCKS, SCAN_BLK>>>();
    scan2_kernel<<<1, 32>>>();
    scan3_kernel<<<NB, 256>>>();
    scatter_kernel<<<EB, 256>>>(esrc, edst);
    aggregate_kernel<<<(N_NODES * 32 + 255) / 256, 256>>>(out);
}

// round 6
// speedup vs baseline: 2.1853x; 1.0337x over previous
#include <cuda_runtime.h>
#include <cuda_fp16.h>
#include <math.h>

#define N_NODES 100000
#define N_EDGES 3200000
#define IN_F 256
#define OUT_F 64
#define ALPHA 0.2f
#define SCAN_BLK 1024
#define N_SCAN_BLOCKS ((N_NODES + SCAN_BLK - 1) / SCAN_BLK)   // 98

// Scratch (static device globals: allocation-free)
__device__ __half2 g_h2[(size_t)N_NODES * 32];     // h in fp16, 12.8 MB (32 half2 per row)
__device__ float   g_ssrc[N_NODES];
__device__ float   g_sdst[N_NODES];
__device__ int     g_count[N_NODES];
__device__ int     g_start[N_NODES];
__device__ int     g_cursor[N_NODES];
__device__ int     g_bsum[N_SCAN_BLOCKS];
__device__ int     g_boff[N_SCAN_BLOCKS];
__device__ float2  g_edge[N_EDGES];                // (.x = dst as int bits, .y = ee)

// ---------------------------------------------------------------------------
// Zero histogram counters
// ---------------------------------------------------------------------------
__global__ void zero_kernel() {
    int i = blockIdx.x * blockDim.x + threadIdx.x;
    if (i < N_NODES) g_count[i] = 0;
}

// ---------------------------------------------------------------------------
// GEMM: h = input @ W  (64x64 tile per block, 4x4 register tile per thread)
// Fused epilogue: s_src = h·a[0:64], s_dst = h·a[64:128]; h stored as fp16.
// ---------------------------------------------------------------------------
__global__ __launch_bounds__(256) void gemm_kernel(const float* __restrict__ inp,
                                                   const float* __restrict__ W,
                                                   const float* __restrict__ a) {
    __shared__ float As[32][64];   // [k][row]  (transposed input tile)
    __shared__ float Bs[32][64];   // [k][col]
    const int tid = threadIdx.x;
    const int tx  = tid & 15;      // col group (4 cols)
    const int ty  = tid >> 4;      // row group (4 rows)
    const int rowbase = blockIdx.x * 64;

    float acc[4][4];
#pragma unroll
    for (int r = 0; r < 4; r++)
#pragma unroll
        for (int c = 0; c < 4; c++) acc[r][c] = 0.f;

    for (int kb = 0; kb < IN_F; kb += 32) {
#pragma unroll
        for (int i = 0; i < 2; i++) {
            int idx = tid * 2 + i;        // 0..511
            int r   = idx >> 3;           // 0..63
            int kq  = idx & 7;            // k-quad
            int grow = rowbase + r;
            float4 v = make_float4(0.f, 0.f, 0.f, 0.f);
            if (grow < N_NODES)
                v = *(const float4*)(inp + (size_t)grow * IN_F + kb + kq * 4);
            As[kq * 4 + 0][r] = v.x;
            As[kq * 4 + 1][r] = v.y;
            As[kq * 4 + 2][r] = v.z;
            As[kq * 4 + 3][r] = v.w;
        }
#pragma unroll
        for (int i = 0; i < 2; i++) {
            int idx = tid * 2 + i;
            int kk  = idx >> 4;           // 0..31
            int cq  = idx & 15;           // col-quad
            *(float4*)&Bs[kk][cq * 4] =
                *(const float4*)(W + (size_t)(kb + kk) * OUT_F + cq * 4);
        }
        __syncthreads();
#pragma unroll
        for (int kk = 0; kk < 32; kk++) {
            float4 av = *(float4*)&As[kk][ty * 4];
            float4 bv = *(float4*)&Bs[kk][tx * 4];
            acc[0][0] += av.x * bv.x; acc[0][1] += av.x * bv.y; acc[0][2] += av.x * bv.z; acc[0][3] += av.x * bv.w;
            acc[1][0] += av.y * bv.x; acc[1][1] += av.y * bv.y; acc[1][2] += av.y * bv.z; acc[1][3] += av.y * bv.w;
            acc[2][0] += av.z * bv.x; acc[2][1] += av.z * bv.y; acc[2][2] += av.z * bv.z; acc[2][3] += av.z * bv.w;
            acc[3][0] += av.w * bv.x; acc[3][1] += av.w * bv.y; acc[3][2] += av.w * bv.z; acc[3][3] += av.w * bv.w;
        }
        __syncthreads();
    }

    // a slices for this thread's 4 columns
    float as0 = a[tx * 4 + 0], as1 = a[tx * 4 + 1], as2 = a[tx * 4 + 2], as3 = a[tx * 4 + 3];
    float ad0 = a[64 + tx * 4 + 0], ad1 = a[64 + tx * 4 + 1], ad2 = a[64 + tx * 4 + 2], ad3 = a[64 + tx * 4 + 3];

#pragma unroll
    for (int r = 0; r < 4; r++) {
        int grow = rowbase + ty * 4 + r;
        // partial dots over this thread's 4 cols
        float ss = acc[r][0] * as0 + acc[r][1] * as1 + acc[r][2] * as2 + acc[r][3] * as3;
        float sd = acc[r][0] * ad0 + acc[r][1] * ad1 + acc[r][2] * ad2 + acc[r][3] * ad3;
        // reduce across the 16 lanes (same ty group) of the half-warp
#pragma unroll
        for (int o = 8; o; o >>= 1) {
            ss += __shfl_xor_sync(0xFFFFFFFFu, ss, o);
            sd += __shfl_xor_sync(0xFFFFFFFFu, sd, o);
        }
        if (grow < N_NODES) {
            if (tx == 0) { g_ssrc[grow] = ss; g_sdst[grow] = sd; }
            // store h row as fp16: this thread covers half2 slots tx*2, tx*2+1
            g_h2[(size_t)grow * 32 + tx * 2 + 0] = __floats2half2_rn(acc[r][0], acc[r][1]);
            g_h2[(size_t)grow * 32 + tx * 2 + 1] = __floats2half2_rn(acc[r][2], acc[r][3]);
        }
    }
}

// ---------------------------------------------------------------------------
// Histogram of src (vectorized: 4 edges per thread)
// ---------------------------------------------------------------------------
__global__ __launch_bounds__(256) void hist_kernel(const int* __restrict__ esrc) {
    int i = blockIdx.x * blockDim.x + threadIdx.x;
    if (i < N_EDGES / 4) {
        int4 s4 = ((const int4*)esrc)[i];
        if ((unsigned)s4.x < N_NODES) atomicAdd(&g_count[s4.x], 1);
        if ((unsigned)s4.y < N_NODES) atomicAdd(&g_count[s4.y], 1);
        if ((unsigned)s4.z < N_NODES) atomicAdd(&g_count[s4.z], 1);
        if ((unsigned)s4.w < N_NODES) atomicAdd(&g_count[s4.w], 1);
    }
}

// ---------------------------------------------------------------------------
// Exclusive scan (3 kernels)
// ---------------------------------------------------------------------------
__global__ __launch_bounds__(SCAN_BLK) void scan1_kernel() {
    __shared__ int sm[SCAN_BLK];
    int tid = threadIdx.x;
    int gid = blockIdx.x * SCAN_BLK + tid;
    int v = (gid < N_NODES) ? g_count[gid] : 0;
    sm[tid] = v;
    __syncthreads();
#pragma unroll
    for (int off = 1; off < SCAN_BLK; off <<= 1) {
        int t = (tid >= off) ? sm[tid - off] : 0;
        __syncthreads();
        sm[tid] += t;
        __syncthreads();
    }
    if (gid < N_NODES) g_start[gid] = sm[tid] - v;  // exclusive
    if (tid == SCAN_BLK - 1) g_bsum[blockIdx.x] = sm[tid];
}

__global__ void scan2_kernel() {
    if (threadIdx.x == 0) {
        int run = 0;
        for (int b = 0; b < N_SCAN_BLOCKS; b++) {
            int t = g_bsum[b];
            g_boff[b] = run;
            run += t;
        }
    }
}

__global__ __launch_bounds__(256) void scan3_kernel() {
    int i = blockIdx.x * blockDim.x + threadIdx.x;
    if (i >= N_NODES) return;
    int st = g_start[i] + g_boff[i >> 10];
    g_start[i]  = st;
    g_cursor[i] = st;
}

// ---------------------------------------------------------------------------
// Scatter: place (dst, ee) into CSR slot of src
// ---------------------------------------------------------------------------
__global__ __launch_bounds__(256) void scatter_kernel(const int* __restrict__ esrc,
                                                      const int* __restrict__ edst) {
    int e = blockIdx.x * blockDim.x + threadIdx.x;
    if (e >= N_EDGES) return;
    int s = esrc[e];
    int d = edst[e];
    if ((unsigned)s >= N_NODES || (unsigned)d >= N_NODES) return;

    float sc = g_ssrc[s] + g_sdst[d];
    float lr = sc > 0.f ? sc : ALPHA * sc;
    float ee = __expf(-lr);

    int pos = atomicAdd(&g_cursor[s], 1);
    g_edge[pos] = make_float2(__int_as_float(d), ee);
}

// ---------------------------------------------------------------------------
// Aggregate: 1 warp per node; fp16 h gather (128B/edge); fused ELU + store
// ---------------------------------------------------------------------------
__global__ __launch_bounds__(256) void aggregate_kernel(float* __restrict__ out) {
    int node = (blockIdx.x * blockDim.x + threadIdx.x) >> 5;
    int lane = threadIdx.x & 31;
    if (node >= N_NODES) return;

    int start = g_start[node];
    int end   = start + g_count[node];

    float accx = 0.f, accy = 0.f, rs = 0.f;
    int i = start;
    for (; i + 4 <= end; i += 4) {
        float2 e0 = g_edge[i + 0];
        float2 e1 = g_edge[i + 1];
        float2 e2 = g_edge[i + 2];
        float2 e3 = g_edge[i + 3];
        float2 v0 = __half22float2(g_h2[(size_t)__float_as_int(e0.x) * 32 + lane]);
        float2 v1 = __half22float2(g_h2[(size_t)__float_as_int(e1.x) * 32 + lane]);
        float2 v2 = __half22float2(g_h2[(size_t)__float_as_int(e2.x) * 32 + lane]);
        float2 v3 = __half22float2(g_h2[(size_t)__float_as_int(e3.x) * 32 + lane]);
        accx += e0.y * v0.x; accy += e0.y * v0.y;
        accx += e1.y * v1.x; accy += e1.y * v1.y;
        accx += e2.y * v2.x; accy += e2.y * v2.y;
        accx += e3.y * v3.x; accy += e3.y * v3.y;
        rs += e0.y + e1.y + e2.y + e3.y;
    }
    for (; i < end; i++) {
        float2 er = g_edge[i];
        float2 v = __half22float2(g_h2[(size_t)__float_as_int(er.x) * 32 + lane]);
        accx += er.y * v.x;
        accy += er.y * v.y;
        rs += er.y;
    }

    float inv = 1.f / rs;
    float o0 = accx * inv;
    float o1 = accy * inv;
    o0 = o0 > 0.f ? o0 : expm1f(o0);
    o1 = o1 > 0.f ? o1 : expm1f(o1);
    ((float2*)out)[(size_t)node * 32 + lane] = make_float2(o0, o1);
}

// ---------------------------------------------------------------------------
extern "C" void kernel_launch(void* const* d_in, const int* in_sizes, int n_in,
                              void* d_out, int out_size) {
    const float* inp  = (const float*)d_in[0];
    const int*   edge = (const int*)d_in[1];     // int32 (JAX default x64-off)
    const float* W    = (const float*)d_in[2];
    const float* a    = (const float*)d_in[3];
    float*       out  = (float*)d_out;

    const int* esrc = edge;
    const int* edst = edge + N_EDGES;

    const int EB = (N_EDGES + 255) / 256;          // 12500
    const int NB = (N_NODES + 255) / 256;          // 391

    zero_kernel<<<NB, 256>>>();
    gemm_kernel<<<(N_NODES + 63) / 64, 256>>>(inp, W, a);
    hist_kernel<<<(N_EDGES / 4 + 255) / 256, 256>>>(esrc);
    scan1_kernel<<<N_SCAN_BLOCKS, SCAN_BLK>>>();
    scan2_kernel<<<1, 32>>>();
    scan3_kernel<<<NB, 256>>>();
    scatter_kernel<<<EB, 256>>>(esrc, edst);
    aggregate_kernel<<<(N_NODES * 32 + 255) / 256, 256>>>(out);
}